// round 1
// baseline (speedup 1.0000x reference)
#include <cuda_runtime.h>

// ============================================================================
// KAN FFN (2 layers) on GB300/B200.
//
// Both layers reduce to GEMMs over a 7-wide per-scalar feature expansion:
//   feats(x) = [ silu(x), B3_0(x), ..., B3_5(x) ]   (cubic B-splines, uniform grid)
//   y[n,o]   = sum_i sum_c feats(x[n,i])[c] * W[i,c,o]
// with fused weight W[i,0,o] = scale_base[i,o], W[i,1+g,o] = coef[i,o,g]*scale_sp[i,o].
//
// Layer 1: N=16384, K=1024*7=7168, M=128
// Layer 2: N=16384, K= 128*7= 896, M=1024
// Total ~30 G-FMA fp32 -> FP32-FMA bound; classic SGEMM tiling with the
// A-tile featurized on the fly from x.
// ============================================================================

#define D1 1024   // d_model
#define H1 128    // kan hidden
#define NCOEF 7   // 1 base (silu) + 6 spline coefficients
#define MAXROWS 16384

__device__ float g_W1[D1 * NCOEF * H1];   // (7168, 128) row-major
__device__ float g_W2[H1 * NCOEF * D1];   // (896, 1024) row-major
__device__ float g_y1[MAXROWS * H1];      // layer-1 output

// ---------------------------------------------------------------------------
// Feature function: silu + 6 cubic B-spline basis values.
// Grid: g(t) = (t-3)*h - 1, h = 2/3, t = 0..9.  Matches the jax reference:
//   degree-0 indicator on [g_t, g_{t+1}), Cox-de-Boor up to degree 3.
// All grid constants fold at compile time after full unroll.
// ---------------------------------------------------------------------------
__device__ __forceinline__ void kan_feats(float x, float* f) {
    const float h = 2.0f / 3.0f;
    float B[9];
#pragma unroll
    for (int t = 0; t < 9; ++t) {
        float gl = (float)(t - 3) * h - 1.0f;
        float gr = (float)(t - 2) * h - 1.0f;
        B[t] = (x >= gl && x < gr) ? 1.0f : 0.0f;
    }
#pragma unroll
    for (int d = 1; d <= 3; ++d) {
#pragma unroll
        for (int t = 0; t + d < 9; ++t) {
            float g_t   = (float)(t - 3) * h - 1.0f;       // g[t]
            float g_t1  = (float)(t - 2) * h - 1.0f;       // g[t+1]
            float g_td  = (float)(t + d - 3) * h - 1.0f;   // g[t+d]
            float g_td1 = (float)(t + d - 2) * h - 1.0f;   // g[t+d+1]
            float inv_l = 1.0f / (g_td - g_t);             // constant-folded
            float inv_r = 1.0f / (g_td1 - g_t1);           // constant-folded
            B[t] = (x - g_t) * inv_l * B[t] + (g_td1 - x) * inv_r * B[t + 1];
        }
    }
    float sig = 1.0f / (1.0f + __expf(-x));
    f[0] = x * sig;
#pragma unroll
    for (int t = 0; t < 6; ++t) f[1 + t] = B[t];
}

// ---------------------------------------------------------------------------
// Fuse (coef, scale_base, scale_sp) -> W[(i*7 + c) * OUT + o]
// coef is (IN, OUT, 6) row-major; scales are (IN, OUT).
// ---------------------------------------------------------------------------
template <int IN, int OUT>
__global__ void prep_w(const float* __restrict__ coef,
                       const float* __restrict__ sb,
                       const float* __restrict__ sp,
                       float* __restrict__ W) {
    int idx = blockIdx.x * blockDim.x + threadIdx.x;
    if (idx >= IN * OUT) return;
    int i = idx / OUT;
    int o = idx - i * OUT;
    W[(size_t)(i * NCOEF) * OUT + o] = sb[idx];
    float s = sp[idx];
#pragma unroll
    for (int g = 0; g < 6; ++g)
        W[(size_t)(i * NCOEF + 1 + g) * OUT + o] = coef[(size_t)idx * 6 + g] * s;
}

// ---------------------------------------------------------------------------
// Fused featurize + GEMM.
// Block tile: 64 rows x 128 cols, 128 threads, 8x8 microtile.
// K-chunk: 8 input dims -> 56 feature-k's per chunk.
// A-tile (56 x 64) is built on the fly from x (each thread: 4 scalars -> 28 feats).
// B-tile (56 x 128) streamed from the fused weight (L2-resident).
// ---------------------------------------------------------------------------
template <int IN, int OUT>
__launch_bounds__(128)
__global__ void kan_gemm(const float* __restrict__ X,
                         const float* __restrict__ W,
                         float* __restrict__ Y, int nrows) {
    constexpr int TK = 56;  // 8 dims * 7 feats
    __shared__ float A_s[TK][64];
    __shared__ float B_s[TK][128];

    const int row0 = blockIdx.x * 64;
    const int col0 = blockIdx.y * 128;
    const int t  = threadIdx.x;
    const int tx = t & 15;   // 16 col-threads * 8 cols = 128
    const int ty = t >> 4;   // 8 row-threads  * 8 rows = 64
    const int r    = t >> 1; // A-fill: row 0..63
    const int half = t & 1;  // A-fill: dim-half (4 dims each)

    float acc[8][8];
#pragma unroll
    for (int i = 0; i < 8; ++i)
#pragma unroll
        for (int j = 0; j < 8; ++j) acc[i][j] = 0.0f;

    for (int i0 = 0; i0 < IN; i0 += 8) {
        // ---- A fill: featurize x[row0..row0+63][i0..i0+7] ----
        {
            int row = row0 + r;
            if (row >= nrows) row = nrows - 1;  // duplicate last row; writes are guarded
            const float4 xv = *reinterpret_cast<const float4*>(
                &X[(size_t)row * IN + i0 + half * 4]);
            float xs[4] = {xv.x, xv.y, xv.z, xv.w};
#pragma unroll
            for (int j = 0; j < 4; ++j) {
                float f[7];
                kan_feats(xs[j], f);
                const int kb = (half * 4 + j) * 7;
#pragma unroll
                for (int c = 0; c < 7; ++c) A_s[kb + c][r] = f[c];
            }
        }
        // ---- B fill: W[i0*7 .. i0*7+55][col0 .. col0+127] ----
#pragma unroll
        for (int it = 0; it < 14; ++it) {
            int idx = it * 128 + t;          // 56 rows * 32 float4
            int kr  = idx >> 5;
            int c4  = (idx & 31) << 2;
            *reinterpret_cast<float4*>(&B_s[kr][c4]) =
                *reinterpret_cast<const float4*>(
                    &W[(size_t)(i0 * 7 + kr) * OUT + col0 + c4]);
        }
        __syncthreads();

        // ---- 64x128x56 compute ----
#pragma unroll 4
        for (int kk = 0; kk < TK; ++kk) {
            float a[8], b[8];
            *reinterpret_cast<float4*>(&a[0]) =
                *reinterpret_cast<const float4*>(&A_s[kk][ty * 8]);
            *reinterpret_cast<float4*>(&a[4]) =
                *reinterpret_cast<const float4*>(&A_s[kk][ty * 8 + 4]);
            *reinterpret_cast<float4*>(&b[0]) =
                *reinterpret_cast<const float4*>(&B_s[kk][tx * 8]);
            *reinterpret_cast<float4*>(&b[4]) =
                *reinterpret_cast<const float4*>(&B_s[kk][tx * 8 + 4]);
#pragma unroll
            for (int i = 0; i < 8; ++i)
#pragma unroll
                for (int j = 0; j < 8; ++j)
                    acc[i][j] = fmaf(a[i], b[j], acc[i][j]);
        }
        __syncthreads();
    }

    // ---- writeout ----
#pragma unroll
    for (int i = 0; i < 8; ++i) {
        int row = row0 + ty * 8 + i;
        if (row < nrows) {
            float4* dst = reinterpret_cast<float4*>(
                &Y[(size_t)row * OUT + col0 + tx * 8]);
            dst[0] = make_float4(acc[i][0], acc[i][1], acc[i][2], acc[i][3]);
            dst[1] = make_float4(acc[i][4], acc[i][5], acc[i][6], acc[i][7]);
        }
    }
}

// ---------------------------------------------------------------------------
// Inputs (metadata order): x, coef1, scale_base1, scale_sp1,
//                          coef2, scale_base2, scale_sp2.  Output: fp32.
// Graph-capturable: kernel launches only; scratch via __device__ globals.
// ---------------------------------------------------------------------------
extern "C" void kernel_launch(void* const* d_in, const int* in_sizes, int n_in,
                              void* d_out, int out_size) {
    const float* x   = (const float*)d_in[0];
    const float* c1  = (const float*)d_in[1];
    const float* sb1 = (const float*)d_in[2];
    const float* sp1 = (const float*)d_in[3];
    const float* c2  = (const float*)d_in[4];
    const float* sb2 = (const float*)d_in[5];
    const float* sp2 = (const float*)d_in[6];
    float* out = (float*)d_out;

    const int nrows = in_sizes[0] / D1;   // 16384

    float *W1, *W2, *Y1;
    cudaGetSymbolAddress((void**)&W1, g_W1);
    cudaGetSymbolAddress((void**)&W2, g_W2);
    cudaGetSymbolAddress((void**)&Y1, g_y1);

    prep_w<D1, H1><<<(D1 * H1 + 255) / 256, 256>>>(c1, sb1, sp1, W1);
    prep_w<H1, D1><<<(H1 * D1 + 255) / 256, 256>>>(c2, sb2, sp2, W2);

    const int nrt = (nrows + 63) / 64;
    kan_gemm<D1, H1><<<dim3(nrt, 1), 128>>>(x,  W1, Y1,  nrows);
    kan_gemm<H1, D1><<<dim3(nrt, 8), 128>>>(Y1, W2, out, nrows);
}

// round 5
// speedup vs baseline: 1.8334x; 1.8334x over previous
#include <cuda_runtime.h>
#include <cuda_bf16.h>
#include <cstdint>

// ============================================================================
// KAN FFN via mma.sync (HMMA) bf16 with 2-term split (fp32-grade accuracy).
// tcgen05 is unavailable: harness compiles PTX for plain sm_100 (no 'a').
//
// feats(x) = [silu(x), B3_0..B3_5(x), 0]  (8 padded per scalar)
// y[n,o] = sum_{i,c} feats(x[n,i])[c] * W[(i*8+c), o]
// Layer 1: M=16384, N=128,  Kf=8192.  Layer 2: M=16384, N=1024, Kf=1024.
//
// Split v = hi(v)+lo(v) in bf16; acc += Ah*Bh + Ah*Bl + Al*Bh (fp32 regs).
// CTA tile 128x128, 256 thr (8 warps: 4m x 2n, warp tile 32x64), K-chunk 64.
// Single 72KB smem stage, 2 CTAs/SM for cross-CTA fill/compute overlap.
// ============================================================================

#define D1 1024
#define H1 128
#define MAXROWS 16384
#define PADW 36   // b32 words per 64-bf16 row (stride % 32 == 4 -> conflict-free frags)

__device__ __nv_bfloat16 g_W1h[H1 * D1 * 8];
__device__ __nv_bfloat16 g_W1l[H1 * D1 * 8];
__device__ __nv_bfloat16 g_W2h[D1 * H1 * 8];
__device__ __nv_bfloat16 g_W2l[D1 * H1 * 8];
__device__ float g_y1[MAXROWS * H1];

// ---------------- KAN featurization (identical to R1, verified) -------------
__device__ __forceinline__ void kan_feats(float x, float* f) {
    const float h = 2.0f / 3.0f;
    float B[9];
#pragma unroll
    for (int t = 0; t < 9; ++t) {
        float gl = (float)(t - 3) * h - 1.0f;
        float gr = (float)(t - 2) * h - 1.0f;
        B[t] = (x >= gl && x < gr) ? 1.0f : 0.0f;
    }
#pragma unroll
    for (int d = 1; d <= 3; ++d) {
#pragma unroll
        for (int t = 0; t + d < 9; ++t) {
            float g_t   = (float)(t - 3) * h - 1.0f;
            float g_t1  = (float)(t - 2) * h - 1.0f;
            float g_td  = (float)(t + d - 3) * h - 1.0f;
            float g_td1 = (float)(t + d - 2) * h - 1.0f;
            float inv_l = 1.0f / (g_td - g_t);
            float inv_r = 1.0f / (g_td1 - g_t1);
            B[t] = (x - g_t) * inv_l * B[t] + (g_td1 - x) * inv_r * B[t + 1];
        }
    }
    float sig = 1.0f / (1.0f + __expf(-x));
    f[0] = x * sig;
#pragma unroll
    for (int t = 0; t < 6; ++t) f[1 + t] = B[t];
}

// Pack (a,b) -> bf16x2 hi word; lo word gets the bf16 residuals.
__device__ __forceinline__ uint32_t split_pair(float a, float b, uint32_t& lo) {
    __nv_bfloat16 ah = __float2bfloat16(a), bh = __float2bfloat16(b);
    __nv_bfloat16 al = __float2bfloat16(a - __bfloat162float(ah));
    __nv_bfloat16 bl = __float2bfloat16(b - __bfloat162float(bh));
    lo = (uint32_t)__bfloat16_as_ushort(al) | ((uint32_t)__bfloat16_as_ushort(bl) << 16);
    return (uint32_t)__bfloat16_as_ushort(ah) | ((uint32_t)__bfloat16_as_ushort(bh) << 16);
}

__device__ __forceinline__ void mma16816(float* d, const uint32_t* a,
                                         uint32_t b0, uint32_t b1) {
    asm volatile(
        "mma.sync.aligned.m16n8k16.row.col.f32.bf16.bf16.f32 "
        "{%0,%1,%2,%3}, {%4,%5,%6,%7}, {%8,%9}, {%0,%1,%2,%3};"
        : "+f"(d[0]), "+f"(d[1]), "+f"(d[2]), "+f"(d[3])
        : "r"(a[0]), "r"(a[1]), "r"(a[2]), "r"(a[3]), "r"(b0), "r"(b1));
}

// ---------------- Weight prep: fused, transposed, hi/lo bf16 ----------------
// W[o][i*8+c]: c=0 -> scale_base; c=1..6 -> coef*scale_sp; c=7 -> 0.
template <int IN, int OUT>
__global__ void prep_wt(const float* __restrict__ coef,
                        const float* __restrict__ sb,
                        const float* __restrict__ sp,
                        __nv_bfloat16* __restrict__ Whi,
                        __nv_bfloat16* __restrict__ Wlo) {
    int idx = blockIdx.x * blockDim.x + threadIdx.x;
    if (idx >= IN * OUT) return;
    int i = idx / OUT, o = idx - i * OUT;
    float vals[8];
    vals[0] = sb[idx];
    float s = sp[idx];
#pragma unroll
    for (int g = 0; g < 6; ++g) vals[1 + g] = coef[(size_t)idx * 6 + g] * s;
    vals[7] = 0.0f;
    size_t base = (size_t)o * (IN * 8) + (size_t)i * 8;
#pragma unroll
    for (int c = 0; c < 8; ++c) {
        float f = vals[c];
        __nv_bfloat16 hb = __float2bfloat16(f);
        Whi[base + c] = hb;
        Wlo[base + c] = __float2bfloat16(f - __bfloat162float(hb));
    }
}

// ---------------- Fused featurize + mma.sync GEMM ---------------------------
// SMEM words: Ah[128*36] | Al | Bh[128*36] | Bl   (A: [m][k], B: [n][k])
template <int IN, int OUT>
__launch_bounds__(256, 2)
__global__ void kan_mma(const float* __restrict__ X,
                        const __nv_bfloat16* __restrict__ Whi,
                        const __nv_bfloat16* __restrict__ Wlo,
                        float* __restrict__ Y, int nrows) {
    extern __shared__ uint32_t smw[];
    uint32_t* Ah = smw;
    uint32_t* Al = smw + 128 * PADW;
    uint32_t* Bh = smw + 2 * 128 * PADW;
    uint32_t* Bl = smw + 3 * 128 * PADW;

    const int tid  = threadIdx.x;
    const int lane = tid & 31;
    const int wid  = tid >> 5;
    const int wm   = wid & 3;      // 4 m-warps * 32 rows
    const int wn   = wid >> 2;     // 2 n-warps * 64 cols
    const int g    = lane >> 2;
    const int cq   = lane & 3;
    const int row0 = blockIdx.x * 128;
    const int col0 = blockIdx.y * 128;
    const int KF   = IN * 8;
    const int NCH  = IN / 8;

    float acc[2][8][4];
#pragma unroll
    for (int mt = 0; mt < 2; ++mt)
#pragma unroll
        for (int nt = 0; nt < 8; ++nt)
#pragma unroll
            for (int q = 0; q < 4; ++q) acc[mt][nt][q] = 0.0f;

    for (int c = 0; c < NCH; ++c) {
        const int i0 = c * 8;
        __syncthreads();  // previous chunk's compute done before overwrite

        // ---- A fill: thread -> (row = tid/2, 4 dims); 8 feats/dim ----
        {
            const int r = tid >> 1, half = tid & 1;
            int row = row0 + r;
            if (row >= nrows) row = nrows - 1;
            const float4 xv = *reinterpret_cast<const float4*>(
                &X[(size_t)row * IN + i0 + half * 4]);
            float xs[4] = {xv.x, xv.y, xv.z, xv.w};
#pragma unroll
            for (int j = 0; j < 4; ++j) {
                float f[7];
                kan_feats(xs[j], f);
                const int d = half * 4 + j;
#pragma unroll
                for (int p = 0; p < 4; ++p) {
                    float a = f[2 * p];
                    float b = (2 * p + 1 < 7) ? f[2 * p + 1] : 0.0f;
                    uint32_t lo, hi = split_pair(a, b, lo);
                    const int wi = r * PADW + d * 4 + p;
                    Ah[wi] = hi;
                    Al[wi] = lo;
                }
            }
        }
        // ---- B fill: 2048 float4 (hi+lo), 8 per thread ----
#pragma unroll
        for (int it = 0; it < 8; ++it) {
            int li   = it * 256 + tid;
            int part = li >> 10;          // 0 = hi, 1 = lo
            int rem  = li & 1023;
            int brow = rem >> 3, jf4 = rem & 7;
            const __nv_bfloat16* Wp = part ? Wlo : Whi;
            const float4 v = *reinterpret_cast<const float4*>(
                &Wp[(size_t)(col0 + brow) * KF + i0 * 8 + jf4 * 8]);
            uint32_t* dst = (part ? Bl : Bh) + brow * PADW + jf4 * 4;
            dst[0] = __float_as_uint(v.x);
            dst[1] = __float_as_uint(v.y);
            dst[2] = __float_as_uint(v.z);
            dst[3] = __float_as_uint(v.w);
        }
        __syncthreads();

        // ---- compute: 4 k16 steps, 3 split passes each ----
#pragma unroll
        for (int ks = 0; ks < 4; ++ks) {
            uint32_t fa_h[2][4], fa_l[2][4];
#pragma unroll
            for (int mt = 0; mt < 2; ++mt) {
                const int rowA = wm * 32 + mt * 16 + g;
                const int base = rowA * PADW + ks * 8 + cq;
                fa_h[mt][0] = Ah[base];
                fa_h[mt][1] = Ah[base + 8 * PADW];
                fa_h[mt][2] = Ah[base + 4];
                fa_h[mt][3] = Ah[base + 8 * PADW + 4];
                fa_l[mt][0] = Al[base];
                fa_l[mt][1] = Al[base + 8 * PADW];
                fa_l[mt][2] = Al[base + 4];
                fa_l[mt][3] = Al[base + 8 * PADW + 4];
            }
#pragma unroll
            for (int nt = 0; nt < 8; ++nt) {
                const int rowB = wn * 64 + nt * 8 + g;
                const int bb = rowB * PADW + ks * 8 + cq;
                const uint32_t bh0 = Bh[bb], bh1 = Bh[bb + 4];
                const uint32_t bl0 = Bl[bb], bl1 = Bl[bb + 4];
#pragma unroll
                for (int mt = 0; mt < 2; ++mt) {
                    mma16816(acc[mt][nt], fa_h[mt], bh0, bh1);
                    mma16816(acc[mt][nt], fa_h[mt], bl0, bl1);
                    mma16816(acc[mt][nt], fa_l[mt], bh0, bh1);
                }
            }
        }
    }

    // ---- epilogue: D[g / g+8][2cq / 2cq+1] per 16x8 tile ----
#pragma unroll
    for (int mt = 0; mt < 2; ++mt) {
        const int rowA = row0 + wm * 32 + mt * 16 + g;
#pragma unroll
        for (int nt = 0; nt < 8; ++nt) {
            const int col = col0 + wn * 64 + nt * 8 + cq * 2;
            if (rowA < nrows)
                *reinterpret_cast<float2*>(&Y[(size_t)rowA * OUT + col]) =
                    make_float2(acc[mt][nt][0], acc[mt][nt][1]);
            if (rowA + 8 < nrows)
                *reinterpret_cast<float2*>(&Y[(size_t)(rowA + 8) * OUT + col]) =
                    make_float2(acc[mt][nt][2], acc[mt][nt][3]);
        }
    }
}

// ---------------------------------------------------------------------------
extern "C" void kernel_launch(void* const* d_in, const int* in_sizes, int n_in,
                              void* d_out, int out_size) {
    const float* x   = (const float*)d_in[0];
    const float* c1  = (const float*)d_in[1];
    const float* sb1 = (const float*)d_in[2];
    const float* sp1 = (const float*)d_in[3];
    const float* c2  = (const float*)d_in[4];
    const float* sb2 = (const float*)d_in[5];
    const float* sp2 = (const float*)d_in[6];
    float* out = (float*)d_out;

    const int nrows = in_sizes[0] / D1;  // 16384
    const int smem  = 4 * 128 * PADW * 4;  // 73728 B

    __nv_bfloat16 *W1h, *W1l, *W2h, *W2l;
    float* Y1;
    cudaGetSymbolAddress((void**)&W1h, g_W1h);
    cudaGetSymbolAddress((void**)&W1l, g_W1l);
    cudaGetSymbolAddress((void**)&W2h, g_W2h);
    cudaGetSymbolAddress((void**)&W2l, g_W2l);
    cudaGetSymbolAddress((void**)&Y1, g_y1);

    cudaFuncSetAttribute(kan_mma<D1, H1>,
                         cudaFuncAttributeMaxDynamicSharedMemorySize, smem);
    cudaFuncSetAttribute(kan_mma<H1, D1>,
                         cudaFuncAttributeMaxDynamicSharedMemorySize, smem);

    prep_wt<D1, H1><<<(D1 * H1 + 255) / 256, 256>>>(c1, sb1, sp1, W1h, W1l);
    prep_wt<H1, D1><<<(H1 * D1 + 255) / 256, 256>>>(c2, sb2, sp2, W2h, W2l);

    const int nrt = (nrows + 127) / 128;
    kan_mma<D1, H1><<<dim3(nrt, 1), 256, smem>>>(x,  W1h, W1l, Y1,  nrows);
    kan_mma<H1, D1><<<dim3(nrt, 8), 256, smem>>>(Y1, W2h, W2l, out, nrows);
}

// round 7
// speedup vs baseline: 2.1588x; 1.1775x over previous
#include <cuda_runtime.h>
#include <cuda_bf16.h>
#include <cstdint>

// ============================================================================
// KAN FFN via mma.sync (HMMA) bf16, 2-term split, ldmatrix fragment loads.
//
// R6 changes vs R5 (895us):
//  - ldmatrix.m8n8.x4 for A/B fragments (48 LDS.32 -> 12 ldmatrix per k16)
//  - layer 1 split-K=2 -> 256 CTAs (was 128 on 148 SMs)
//  - y1 featurized ONCE by feat2 kernel (was 8x redundant in layer-2 CTAs)
// ============================================================================

#define D1 1024
#define H1 128
#define MAXROWS 16384
#define PADW 36              // words per 64-bf16 smem row; stride%32==4 -> conflict-free
#define ALOFF (128 * PADW * 4)  // bytes per smem plane (18432)

__device__ __nv_bfloat16 g_W1h[H1 * D1 * 8];
__device__ __nv_bfloat16 g_W1l[H1 * D1 * 8];
__device__ __nv_bfloat16 g_W2h[D1 * H1 * 8];
__device__ __nv_bfloat16 g_W2l[D1 * H1 * 8];
__device__ float g_y1p[2 * MAXROWS * H1];          // layer-1 split-K partials
__device__ __nv_bfloat16 g_A2h[MAXROWS * H1 * 8];  // layer-2 A features hi
__device__ __nv_bfloat16 g_A2l[MAXROWS * H1 * 8];  // layer-2 A features lo

// ---------------- KAN featurization (verified R1) ---------------------------
__device__ __forceinline__ void kan_feats(float x, float* f) {
    const float h = 2.0f / 3.0f;
    float B[9];
#pragma unroll
    for (int t = 0; t < 9; ++t) {
        float gl = (float)(t - 3) * h - 1.0f;
        float gr = (float)(t - 2) * h - 1.0f;
        B[t] = (x >= gl && x < gr) ? 1.0f : 0.0f;
    }
#pragma unroll
    for (int d = 1; d <= 3; ++d) {
#pragma unroll
        for (int t = 0; t + d < 9; ++t) {
            float g_t   = (float)(t - 3) * h - 1.0f;
            float g_t1  = (float)(t - 2) * h - 1.0f;
            float g_td  = (float)(t + d - 3) * h - 1.0f;
            float g_td1 = (float)(t + d - 2) * h - 1.0f;
            float inv_l = 1.0f / (g_td - g_t);
            float inv_r = 1.0f / (g_td1 - g_t1);
            B[t] = (x - g_t) * inv_l * B[t] + (g_td1 - x) * inv_r * B[t + 1];
        }
    }
    float sig = 1.0f / (1.0f + __expf(-x));
    f[0] = x * sig;
#pragma unroll
    for (int t = 0; t < 6; ++t) f[1 + t] = B[t];
}

__device__ __forceinline__ uint32_t split_pair(float a, float b, uint32_t& lo) {
    __nv_bfloat16 ah = __float2bfloat16(a), bh = __float2bfloat16(b);
    __nv_bfloat16 al = __float2bfloat16(a - __bfloat162float(ah));
    __nv_bfloat16 bl = __float2bfloat16(b - __bfloat162float(bh));
    lo = (uint32_t)__bfloat16_as_ushort(al) | ((uint32_t)__bfloat16_as_ushort(bl) << 16);
    return (uint32_t)__bfloat16_as_ushort(ah) | ((uint32_t)__bfloat16_as_ushort(bh) << 16);
}

__device__ __forceinline__ void mma16816(float* d, const uint32_t* a,
                                         uint32_t b0, uint32_t b1) {
    asm volatile(
        "mma.sync.aligned.m16n8k16.row.col.f32.bf16.bf16.f32 "
        "{%0,%1,%2,%3}, {%4,%5,%6,%7}, {%8,%9}, {%0,%1,%2,%3};"
        : "+f"(d[0]), "+f"(d[1]), "+f"(d[2]), "+f"(d[3])
        : "r"(a[0]), "r"(a[1]), "r"(a[2]), "r"(a[3]), "r"(b0), "r"(b1));
}

__device__ __forceinline__ void ldm_x4(uint32_t* r, uint32_t addr) {
    asm volatile("ldmatrix.sync.aligned.m8n8.x4.shared.b16 {%0,%1,%2,%3}, [%4];"
                 : "=r"(r[0]), "=r"(r[1]), "=r"(r[2]), "=r"(r[3]) : "r"(addr));
}

// ---------------- Weight prep (unchanged) -----------------------------------
template <int IN, int OUT>
__global__ void prep_wt(const float* __restrict__ coef,
                        const float* __restrict__ sb,
                        const float* __restrict__ sp,
                        __nv_bfloat16* __restrict__ Whi,
                        __nv_bfloat16* __restrict__ Wlo) {
    int idx = blockIdx.x * blockDim.x + threadIdx.x;
    if (idx >= IN * OUT) return;
    int i = idx / OUT, o = idx - i * OUT;
    float vals[8];
    vals[0] = sb[idx];
    float s = sp[idx];
#pragma unroll
    for (int g = 0; g < 6; ++g) vals[1 + g] = coef[(size_t)idx * 6 + g] * s;
    vals[7] = 0.0f;
    size_t base = (size_t)o * (IN * 8) + (size_t)i * 8;
#pragma unroll
    for (int c = 0; c < 8; ++c) {
        float f = vals[c];
        __nv_bfloat16 hb = __float2bfloat16(f);
        Whi[base + c] = hb;
        Wlo[base + c] = __float2bfloat16(f - __bfloat162float(hb));
    }
}

// ---------------- feat2: y1 = p0+p1 -> features -> global bf16 hi/lo --------
__global__ void feat2(const float* __restrict__ p0, const float* __restrict__ p1,
                      __nv_bfloat16* __restrict__ A2h,
                      __nv_bfloat16* __restrict__ A2l, int total) {
    int idx = blockIdx.x * blockDim.x + threadIdx.x;   // scalar over nrows*128
    if (idx >= total) return;
    float y = p0[idx] + p1[idx];
    float f[7];
    kan_feats(y, f);
    uint4 hv, lv;
    uint32_t* hw = reinterpret_cast<uint32_t*>(&hv);
    uint32_t* lw = reinterpret_cast<uint32_t*>(&lv);
#pragma unroll
    for (int p = 0; p < 4; ++p) {
        float a = f[2 * p];
        float b = (2 * p + 1 < 7) ? f[2 * p + 1] : 0.0f;
        hw[p] = split_pair(a, b, lw[p]);
    }
    // A2 layout: [row][dim*8 + c]; idx = row*128 + dim -> byte offset idx*16
    *reinterpret_cast<uint4*>(&A2h[(size_t)idx * 8]) = hv;
    *reinterpret_cast<uint4*>(&A2l[(size_t)idx * 8]) = lv;
}

// ---------------- Fused GEMM: 128x128 tile, 8 warps (4m x 2n) ---------------
// PRE=false: A from X + featurize (layer 1, SPLITK via blockIdx.y).
// PRE=true:  A from precomputed A2h/A2l (layer 2, col tile via blockIdx.y).
template <int IN, int OUT, bool PRE>
__launch_bounds__(256, 2)
__global__ void kan_mma(const float* __restrict__ X,
                        const __nv_bfloat16* __restrict__ A2h,
                        const __nv_bfloat16* __restrict__ A2l,
                        const __nv_bfloat16* __restrict__ Whi,
                        const __nv_bfloat16* __restrict__ Wlo,
                        float* __restrict__ Y, int nrows) {
    extern __shared__ uint32_t smw[];
    uint32_t* Ah = smw;
    uint32_t* Al = smw + 128 * PADW;
    uint32_t* Bh = smw + 2 * 128 * PADW;
    uint32_t* Bl = smw + 3 * 128 * PADW;
    const uint32_t smb = (uint32_t)__cvta_generic_to_shared(smw);

    const int tid  = threadIdx.x;
    const int lane = tid & 31;
    const int wid  = tid >> 5;
    const int wm   = wid & 3;
    const int wn   = wid >> 2;
    const int row0 = blockIdx.x * 128;
    const int KF   = IN * 8;

    int ch0, ch1, col0;
    float* Yb = Y;
    if (PRE) {                       // layer 2: full K, blockIdx.y = col tile
        ch0 = 0; ch1 = IN / 8;
        col0 = blockIdx.y * 128;
    } else {                         // layer 1: split-K, col0 = 0
        const int half = (IN / 8) / 2;
        ch0 = blockIdx.y * half; ch1 = ch0 + half;
        col0 = 0;
        Yb = Y + (size_t)blockIdx.y * nrows * OUT;
    }

    // ldmatrix per-lane base addresses (t = lane>>3, r = lane&7)
    const int lt = lane >> 3, lr = lane & 7;
    uint32_t aBase[2], bBase[4];
#pragma unroll
    for (int mt = 0; mt < 2; ++mt) {
        int rowl = wm * 32 + mt * 16 + (lt & 1) * 8 + lr;
        aBase[mt] = smb + (uint32_t)(rowl * PADW + (lt >> 1) * 4) * 4;
    }
#pragma unroll
    for (int ntp = 0; ntp < 4; ++ntp) {
        int nl = wn * 64 + ntp * 16 + (lt >> 1) * 8 + lr;
        bBase[ntp] = smb + 2 * ALOFF + (uint32_t)(nl * PADW + (lt & 1) * 4) * 4;
    }

    float acc[2][8][4];
#pragma unroll
    for (int mt = 0; mt < 2; ++mt)
#pragma unroll
        for (int nt = 0; nt < 8; ++nt)
#pragma unroll
            for (int q = 0; q < 4; ++q) acc[mt][nt][q] = 0.0f;

    for (int c = ch0; c < ch1; ++c) {
        const int i0 = c * 8;
        __syncthreads();

        // ---- A fill ----
        if (PRE) {
            // load precomputed feats: per chunk 128 rows x 128B (hi + lo)
#pragma unroll
            for (int it = 0; it < 8; ++it) {
                int li   = it * 256 + tid;
                int part = li >> 10;
                int rem  = li & 1023;
                int r = rem >> 3, j = rem & 7;
                int row = row0 + r;
                if (row >= nrows) row = nrows - 1;
                const __nv_bfloat16* Ap = part ? A2l : A2h;
                const uint4 v = *reinterpret_cast<const uint4*>(
                    &Ap[(size_t)row * KF + i0 * 8 + j * 8]);
                uint32_t* dst = (part ? Al : Ah) + r * PADW + j * 4;
                dst[0] = v.x; dst[1] = v.y; dst[2] = v.z; dst[3] = v.w;
            }
        } else {
            const int r = tid >> 1, half = tid & 1;
            int row = row0 + r;
            if (row >= nrows) row = nrows - 1;
            const float4 xv = *reinterpret_cast<const float4*>(
                &X[(size_t)row * IN + i0 + half * 4]);
            float xs[4] = {xv.x, xv.y, xv.z, xv.w};
#pragma unroll
            for (int j = 0; j < 4; ++j) {
                float f[7];
                kan_feats(xs[j], f);
                const int d = half * 4 + j;
#pragma unroll
                for (int p = 0; p < 4; ++p) {
                    float a = f[2 * p];
                    float b = (2 * p + 1 < 7) ? f[2 * p + 1] : 0.0f;
                    uint32_t lo, hi = split_pair(a, b, lo);
                    const int wi = r * PADW + d * 4 + p;
                    Ah[wi] = hi;
                    Al[wi] = lo;
                }
            }
        }
        // ---- B fill: 2048 float4 (hi+lo) ----
#pragma unroll
        for (int it = 0; it < 8; ++it) {
            int li   = it * 256 + tid;
            int part = li >> 10;
            int rem  = li & 1023;
            int brow = rem >> 3, jf4 = rem & 7;
            const __nv_bfloat16* Wp = part ? Wlo : Whi;
            const uint4 v = *reinterpret_cast<const uint4*>(
                &Wp[(size_t)(col0 + brow) * KF + i0 * 8 + jf4 * 8]);
            uint32_t* dst = (part ? Bl : Bh) + brow * PADW + jf4 * 4;
            dst[0] = v.x; dst[1] = v.y; dst[2] = v.z; dst[3] = v.w;
        }
        __syncthreads();

        // ---- compute: 4 k16 steps, ldmatrix frags, 3 split passes ----
#pragma unroll
        for (int ks = 0; ks < 4; ++ks) {
            const uint32_t ko = ks * 32;   // bytes
            uint32_t ah[2][4], al[2][4];
            ldm_x4(ah[0], aBase[0] + ko);
            ldm_x4(ah[1], aBase[1] + ko);
            ldm_x4(al[0], aBase[0] + ALOFF + ko);
            ldm_x4(al[1], aBase[1] + ALOFF + ko);
#pragma unroll
            for (int ntp = 0; ntp < 4; ++ntp) {
                uint32_t bh[4], bl[4];
                ldm_x4(bh, bBase[ntp] + ko);
                ldm_x4(bl, bBase[ntp] + ALOFF + ko);
#pragma unroll
                for (int sub = 0; sub < 2; ++sub) {
                    const int nt = ntp * 2 + sub;
                    const uint32_t b0h = bh[2 * sub], b1h = bh[2 * sub + 1];
                    const uint32_t b0l = bl[2 * sub], b1l = bl[2 * sub + 1];
#pragma unroll
                    for (int mt = 0; mt < 2; ++mt) {
                        mma16816(acc[mt][nt], ah[mt], b0h, b1h);
                        mma16816(acc[mt][nt], ah[mt], b0l, b1l);
                        mma16816(acc[mt][nt], al[mt], b0h, b1h);
                    }
                }
            }
        }
    }

    // ---- epilogue ----
    const int g  = lane >> 2;
    const int cq = lane & 3;
#pragma unroll
    for (int mt = 0; mt < 2; ++mt) {
        const int rowA = row0 + wm * 32 + mt * 16 + g;
#pragma unroll
        for (int nt = 0; nt < 8; ++nt) {
            const int col = col0 + wn * 64 + nt * 8 + cq * 2;
            if (rowA < nrows)
                *reinterpret_cast<float2*>(&Yb[(size_t)rowA * OUT + col]) =
                    make_float2(acc[mt][nt][0], acc[mt][nt][1]);
            if (rowA + 8 < nrows)
                *reinterpret_cast<float2*>(&Yb[(size_t)(rowA + 8) * OUT + col]) =
                    make_float2(acc[mt][nt][2], acc[mt][nt][3]);
        }
    }
}

// ---------------------------------------------------------------------------
extern "C" void kernel_launch(void* const* d_in, const int* in_sizes, int n_in,
                              void* d_out, int out_size) {
    const float* x   = (const float*)d_in[0];
    const float* c1  = (const float*)d_in[1];
    const float* sb1 = (const float*)d_in[2];
    const float* sp1 = (const float*)d_in[3];
    const float* c2  = (const float*)d_in[4];
    const float* sb2 = (const float*)d_in[5];
    const float* sp2 = (const float*)d_in[6];
    float* out = (float*)d_out;

    const int nrows = in_sizes[0] / D1;       // 16384
    const int smem  = 4 * 128 * PADW * 4;     // 73728 B

    __nv_bfloat16 *W1h, *W1l, *W2h, *W2l, *A2h, *A2l;
    float* Y1p;
    cudaGetSymbolAddress((void**)&W1h, g_W1h);
    cudaGetSymbolAddress((void**)&W1l, g_W1l);
    cudaGetSymbolAddress((void**)&W2h, g_W2h);
    cudaGetSymbolAddress((void**)&W2l, g_W2l);
    cudaGetSymbolAddress((void**)&A2h, g_A2h);
    cudaGetSymbolAddress((void**)&A2l, g_A2l);
    cudaGetSymbolAddress((void**)&Y1p, g_y1p);

    cudaFuncSetAttribute((const void*)kan_mma<D1, H1, false>,
                         cudaFuncAttributeMaxDynamicSharedMemorySize, smem);
    cudaFuncSetAttribute((const void*)kan_mma<H1, D1, true>,
                         cudaFuncAttributeMaxDynamicSharedMemorySize, smem);

    prep_wt<D1, H1><<<(D1 * H1 + 255) / 256, 256>>>(c1, sb1, sp1, W1h, W1l);
    prep_wt<H1, D1><<<(H1 * D1 + 255) / 256, 256>>>(c2, sb2, sp2, W2h, W2l);

    const int nrt = (nrows + 127) / 128;
    // layer 1: split-K=2 -> grid (128, 2) = 256 CTAs
    kan_mma<D1, H1, false><<<dim3(nrt, 2), 256, smem>>>(
        x, nullptr, nullptr, W1h, W1l, Y1p, nrows);
    // featurize y1 once
    const int tot = nrows * H1;
    feat2<<<(tot + 255) / 256, 256>>>(Y1p, Y1p + (size_t)nrows * H1, A2h, A2l, tot);
    // layer 2: precomputed A -> grid (128, 8)
    kan_mma<H1, D1, true><<<dim3(nrt, 8), 256, smem>>>(
        nullptr, A2h, A2l, W2h, W2l, out, nrows);
}

// round 10
// speedup vs baseline: 2.2680x; 1.0506x over previous
#include <cuda_runtime.h>
#include <cuda_bf16.h>
#include <cstdint>

// ============================================================================
// KAN FFN via mma.sync (HMMA) bf16, 2-term split, ldmatrix, double-buffered.
//
// R8 vs R7 (760us): 2-stage smem pipeline (K-chunk 32 feats, 40KB/stage,
// still 2 CTAs/SM) + cp.async fills -> overlap fill with tensor-pipe MMAs.
// ============================================================================

#define D1 1024
#define H1 128
#define MAXROWS 16384
#define PADW 20                   // words per 32-feat row (16 data + 4 pad)
#define PB   (128 * PADW * 4)     // plane bytes (10240)
#define SB   (4 * PB)             // stage bytes  (40960): Ah|Al|Bh|Bl

__device__ __nv_bfloat16 g_W1h[H1 * D1 * 8];
__device__ __nv_bfloat16 g_W1l[H1 * D1 * 8];
__device__ __nv_bfloat16 g_W2h[D1 * H1 * 8];
__device__ __nv_bfloat16 g_W2l[D1 * H1 * 8];
__device__ float g_y1p[2 * MAXROWS * H1];
__device__ __nv_bfloat16 g_A2h[MAXROWS * H1 * 8];
__device__ __nv_bfloat16 g_A2l[MAXROWS * H1 * 8];

// ---------------- KAN featurization (verified R1) ---------------------------
__device__ __forceinline__ void kan_feats(float x, float* f) {
    const float h = 2.0f / 3.0f;
    float B[9];
#pragma unroll
    for (int t = 0; t < 9; ++t) {
        float gl = (float)(t - 3) * h - 1.0f;
        float gr = (float)(t - 2) * h - 1.0f;
        B[t] = (x >= gl && x < gr) ? 1.0f : 0.0f;
    }
#pragma unroll
    for (int d = 1; d <= 3; ++d) {
#pragma unroll
        for (int t = 0; t + d < 9; ++t) {
            float g_t   = (float)(t - 3) * h - 1.0f;
            float g_t1  = (float)(t - 2) * h - 1.0f;
            float g_td  = (float)(t + d - 3) * h - 1.0f;
            float g_td1 = (float)(t + d - 2) * h - 1.0f;
            float inv_l = 1.0f / (g_td - g_t);
            float inv_r = 1.0f / (g_td1 - g_t1);
            B[t] = (x - g_t) * inv_l * B[t] + (g_td1 - x) * inv_r * B[t + 1];
        }
    }
    float sig = 1.0f / (1.0f + __expf(-x));
    f[0] = x * sig;
#pragma unroll
    for (int t = 0; t < 6; ++t) f[1 + t] = B[t];
}

__device__ __forceinline__ uint32_t split_pair(float a, float b, uint32_t& lo) {
    __nv_bfloat16 ah = __float2bfloat16(a), bh = __float2bfloat16(b);
    __nv_bfloat16 al = __float2bfloat16(a - __bfloat162float(ah));
    __nv_bfloat16 bl = __float2bfloat16(b - __bfloat162float(bh));
    lo = (uint32_t)__bfloat16_as_ushort(al) | ((uint32_t)__bfloat16_as_ushort(bl) << 16);
    return (uint32_t)__bfloat16_as_ushort(ah) | ((uint32_t)__bfloat16_as_ushort(bh) << 16);
}

__device__ __forceinline__ void mma16816(float* d, const uint32_t* a,
                                         uint32_t b0, uint32_t b1) {
    asm volatile(
        "mma.sync.aligned.m16n8k16.row.col.f32.bf16.bf16.f32 "
        "{%0,%1,%2,%3}, {%4,%5,%6,%7}, {%8,%9}, {%0,%1,%2,%3};"
        : "+f"(d[0]), "+f"(d[1]), "+f"(d[2]), "+f"(d[3])
        : "r"(a[0]), "r"(a[1]), "r"(a[2]), "r"(a[3]), "r"(b0), "r"(b1));
}

__device__ __forceinline__ void ldm_x4(uint32_t* r, uint32_t addr) {
    asm volatile("ldmatrix.sync.aligned.m8n8.x4.shared.b16 {%0,%1,%2,%3}, [%4];"
                 : "=r"(r[0]), "=r"(r[1]), "=r"(r[2]), "=r"(r[3]) : "r"(addr));
}

__device__ __forceinline__ void cp_async16(uint32_t dst, const void* src) {
    asm volatile("cp.async.cg.shared.global [%0], [%1], 16;"
                 :: "r"(dst), "l"(src) : "memory");
}
__device__ __forceinline__ void cp_commit() {
    asm volatile("cp.async.commit_group;" ::: "memory");
}
__device__ __forceinline__ void cp_wait0() {
    asm volatile("cp.async.wait_group 0;" ::: "memory");
}

// ---------------- Weight prep (unchanged) -----------------------------------
template <int IN, int OUT>
__global__ void prep_wt(const float* __restrict__ coef,
                        const float* __restrict__ sb,
                        const float* __restrict__ sp,
                        __nv_bfloat16* __restrict__ Whi,
                        __nv_bfloat16* __restrict__ Wlo) {
    int idx = blockIdx.x * blockDim.x + threadIdx.x;
    if (idx >= IN * OUT) return;
    int i = idx / OUT, o = idx - i * OUT;
    float vals[8];
    vals[0] = sb[idx];
    float s = sp[idx];
#pragma unroll
    for (int g = 0; g < 6; ++g) vals[1 + g] = coef[(size_t)idx * 6 + g] * s;
    vals[7] = 0.0f;
    size_t base = (size_t)o * (IN * 8) + (size_t)i * 8;
#pragma unroll
    for (int c = 0; c < 8; ++c) {
        float f = vals[c];
        __nv_bfloat16 hb = __float2bfloat16(f);
        Whi[base + c] = hb;
        Wlo[base + c] = __float2bfloat16(f - __bfloat162float(hb));
    }
}

// ---------------- feat2 (unchanged) -----------------------------------------
__global__ void feat2(const float* __restrict__ p0, const float* __restrict__ p1,
                      __nv_bfloat16* __restrict__ A2h,
                      __nv_bfloat16* __restrict__ A2l, int total) {
    int idx = blockIdx.x * blockDim.x + threadIdx.x;
    if (idx >= total) return;
    float y = p0[idx] + p1[idx];
    float f[7];
    kan_feats(y, f);
    uint4 hv, lv;
    uint32_t* hw = reinterpret_cast<uint32_t*>(&hv);
    uint32_t* lw = reinterpret_cast<uint32_t*>(&lv);
#pragma unroll
    for (int p = 0; p < 4; ++p) {
        float a = f[2 * p];
        float b = (2 * p + 1 < 7) ? f[2 * p + 1] : 0.0f;
        hw[p] = split_pair(a, b, lw[p]);
    }
    *reinterpret_cast<uint4*>(&A2h[(size_t)idx * 8]) = hv;
    *reinterpret_cast<uint4*>(&A2l[(size_t)idx * 8]) = lv;
}

// ---------------- Double-buffered fused GEMM --------------------------------
// Stage layout (bytes): Ah[0,PB) Al[PB,2PB) Bh[2PB,3PB) Bl[3PB,4PB); 2 stages.
// K-chunk = 32 feats = 4 input dims.
template <int IN, int OUT, bool PRE>
__launch_bounds__(256, 2)
__global__ void kan_mma(const float* __restrict__ X,
                        const __nv_bfloat16* __restrict__ A2h,
                        const __nv_bfloat16* __restrict__ A2l,
                        const __nv_bfloat16* __restrict__ Whi,
                        const __nv_bfloat16* __restrict__ Wlo,
                        float* __restrict__ Y, int nrows) {
    extern __shared__ uint32_t smw[];
    const uint32_t smb = (uint32_t)__cvta_generic_to_shared(smw);

    const int tid  = threadIdx.x;
    const int lane = tid & 31;
    const int wid  = tid >> 5;
    const int wm   = wid & 3;
    const int wn   = wid >> 2;
    const int row0 = blockIdx.x * 128;
    const int KF   = IN * 8;

    int ch0, ch1, col0;
    float* Yb = Y;
    if (PRE) {                          // layer 2: full K, col tile
        ch0 = 0; ch1 = IN / 4;
        col0 = blockIdx.y * 128;
    } else {                            // layer 1: split-K halves
        const int half = (IN / 4) / 2;
        ch0 = blockIdx.y * half; ch1 = ch0 + half;
        col0 = 0;
        Yb = Y + (size_t)blockIdx.y * nrows * OUT;
    }

    // A-fill row mapping (layer 1): 2 scalars per thread
    const int fr = tid >> 1, fhalf = tid & 1;
    int frow = row0 + fr;
    if (frow >= nrows) frow = nrows - 1;

    // ldmatrix base offsets (within a stage)
    const int lt = lane >> 3, lr = lane & 7;
    uint32_t aOff[2], bOff[4];
#pragma unroll
    for (int mt = 0; mt < 2; ++mt) {
        int rowl = wm * 32 + mt * 16 + (lt & 1) * 8 + lr;
        aOff[mt] = (uint32_t)(rowl * PADW + (lt >> 1) * 4) * 4;
    }
#pragma unroll
    for (int ntp = 0; ntp < 4; ++ntp) {
        int nl = wn * 64 + ntp * 16 + (lt >> 1) * 8 + lr;
        bOff[ntp] = 2 * PB + (uint32_t)(nl * PADW + (lt & 1) * 4) * 4;
    }

    // ---- stage fill helper (chunk c -> stage base sOff) ----
    auto fill = [&](int c, uint32_t sOff) {
        const int i0 = c * 4;  // first input dim of chunk
        if (PRE) {
            // A: 128 rows x 16 words, hi+lo = 1024 uint4 -> 4/thread (cp.async)
#pragma unroll
            for (int it = 0; it < 2; ++it) {
                int li  = it * 256 + tid;        // over 512 uint4 per plane
                int r = li >> 2, j = li & 3;
                int row = row0 + r;
                if (row >= nrows) row = nrows - 1;
                const size_t so = (size_t)row * KF + c * 32 + j * 8;
                uint32_t dw = smb + sOff + (uint32_t)(r * PADW + j * 4) * 4;
                cp_async16(dw, &A2h[so]);
                cp_async16(dw + PB, &A2l[so]);
            }
        } else {
            // featurize 2 scalars -> 8 words STS
            const float2 xv = *reinterpret_cast<const float2*>(
                &X[(size_t)frow * IN + i0 + fhalf * 2]);
            float xs[2] = {xv.x, xv.y};
            uint32_t* Ah = smw + (sOff >> 2) + fr * PADW;
            uint32_t* Al = Ah + (PB >> 2);
#pragma unroll
            for (int j = 0; j < 2; ++j) {
                float f[7];
                kan_feats(xs[j], f);
                const int d = fhalf * 2 + j;
#pragma unroll
                for (int p = 0; p < 4; ++p) {
                    float a = f[2 * p];
                    float b = (2 * p + 1 < 7) ? f[2 * p + 1] : 0.0f;
                    uint32_t lo, hi = split_pair(a, b, lo);
                    Ah[d * 4 + p] = hi;
                    Al[d * 4 + p] = lo;
                }
            }
        }
        // B: 128 rows x 16 words, hi+lo -> 4 uint4/thread (cp.async)
#pragma unroll
        for (int it = 0; it < 2; ++it) {
            int li  = it * 256 + tid;
            int r = li >> 2, j = li & 3;
            const size_t so = (size_t)(col0 + r) * KF + c * 32 + j * 8;
            uint32_t dw = smb + sOff + 2 * PB + (uint32_t)(r * PADW + j * 4) * 4;
            cp_async16(dw, &Whi[so]);
            cp_async16(dw + PB, &Wlo[so]);
        }
        cp_commit();
    };

    float acc[2][8][4];
#pragma unroll
    for (int mt = 0; mt < 2; ++mt)
#pragma unroll
        for (int nt = 0; nt < 8; ++nt)
#pragma unroll
            for (int q = 0; q < 4; ++q) acc[mt][nt][q] = 0.0f;

    // ---- prologue: fill stage 0 ----
    fill(ch0, 0);
    cp_wait0();
    __syncthreads();

    for (int c = ch0; c < ch1; ++c) {
        const uint32_t sOff  = (uint32_t)((c - ch0) & 1) * SB;
        const uint32_t sOffN = sOff ^ SB;

        if (c + 1 < ch1) fill(c + 1, sOffN);

        // ---- MMAs on current stage: 2 k16-steps, 3 split passes ----
#pragma unroll
        for (int ks = 0; ks < 2; ++ks) {
            const uint32_t ko = ks * 32;
            uint32_t ah[2][4], al[2][4];
            ldm_x4(ah[0], smb + sOff + aOff[0] + ko);
            ldm_x4(ah[1], smb + sOff + aOff[1] + ko);
            ldm_x4(al[0], smb + sOff + aOff[0] + PB + ko);
            ldm_x4(al[1], smb + sOff + aOff[1] + PB + ko);
#pragma unroll
            for (int ntp = 0; ntp < 4; ++ntp) {
                uint32_t bh[4], bl[4];
                ldm_x4(bh, smb + sOff + bOff[ntp] + ko);
                ldm_x4(bl, smb + sOff + bOff[ntp] + PB + ko);
#pragma unroll
                for (int sub = 0; sub < 2; ++sub) {
                    const int nt = ntp * 2 + sub;
                    const uint32_t b0h = bh[2 * sub], b1h = bh[2 * sub + 1];
                    const uint32_t b0l = bl[2 * sub], b1l = bl[2 * sub + 1];
#pragma unroll
                    for (int mt = 0; mt < 2; ++mt) {
                        mma16816(acc[mt][nt], ah[mt], b0h, b1h);
                        mma16816(acc[mt][nt], ah[mt], b0l, b1l);
                        mma16816(acc[mt][nt], al[mt], b0h, b1h);
                    }
                }
            }
        }

        cp_wait0();
        __syncthreads();
    }

    // ---- epilogue ----
    const int g  = lane >> 2;
    const int cq = lane & 3;
#pragma unroll
    for (int mt = 0; mt < 2; ++mt) {
        const int rowA = row0 + wm * 32 + mt * 16 + g;
#pragma unroll
        for (int nt = 0; nt < 8; ++nt) {
            const int col = col0 + wn * 64 + nt * 8 + cq * 2;
            if (rowA < nrows)
                *reinterpret_cast<float2*>(&Yb[(size_t)rowA * OUT + col]) =
                    make_float2(acc[mt][nt][0], acc[mt][nt][1]);
            if (rowA + 8 < nrows)
                *reinterpret_cast<float2*>(&Yb[(size_t)(rowA + 8) * OUT + col]) =
                    make_float2(acc[mt][nt][2], acc[mt][nt][3]);
        }
    }
}

// ---------------------------------------------------------------------------
extern "C" void kernel_launch(void* const* d_in, const int* in_sizes, int n_in,
                              void* d_out, int out_size) {
    const float* x   = (const float*)d_in[0];
    const float* c1  = (const float*)d_in[1];
    const float* sb1 = (const float*)d_in[2];
    const float* sp1 = (const float*)d_in[3];
    const float* c2  = (const float*)d_in[4];
    const float* sb2 = (const float*)d_in[5];
    const float* sp2 = (const float*)d_in[6];
    float* out = (float*)d_out;

    const int nrows = in_sizes[0] / D1;   // 16384
    const int smem  = 2 * SB;             // 81920 B

    __nv_bfloat16 *W1h, *W1l, *W2h, *W2l, *A2h, *A2l;
    float* Y1p;
    cudaGetSymbolAddress((void**)&W1h, g_W1h);
    cudaGetSymbolAddress((void**)&W1l, g_W1l);
    cudaGetSymbolAddress((void**)&W2h, g_W2h);
    cudaGetSymbolAddress((void**)&W2l, g_W2l);
    cudaGetSymbolAddress((void**)&A2h, g_A2h);
    cudaGetSymbolAddress((void**)&A2l, g_A2l);
    cudaGetSymbolAddress((void**)&Y1p, g_y1p);

    cudaFuncSetAttribute((const void*)kan_mma<D1, H1, false>,
                         cudaFuncAttributeMaxDynamicSharedMemorySize, smem);
    cudaFuncSetAttribute((const void*)kan_mma<H1, D1, true>,
                         cudaFuncAttributeMaxDynamicSharedMemorySize, smem);

    prep_wt<D1, H1><<<(D1 * H1 + 255) / 256, 256>>>(c1, sb1, sp1, W1h, W1l);
    prep_wt<H1, D1><<<(H1 * D1 + 255) / 256, 256>>>(c2, sb2, sp2, W2h, W2l);

    const int nrt = (nrows + 127) / 128;
    kan_mma<D1, H1, false><<<dim3(nrt, 2), 256, smem>>>(
        x, nullptr, nullptr, W1h, W1l, Y1p, nrows);
    const int tot = nrows * H1;
    feat2<<<(tot + 255) / 256, 256>>>(Y1p, Y1p + (size_t)nrows * H1, A2h, A2l, tot);
    kan_mma<H1, D1, true><<<dim3(nrt, 8), 256, smem>>>(
        nullptr, A2h, A2l, W2h, W2l, out, nrows);
}